// round 6
// baseline (speedup 1.0000x reference)
#include <cuda_runtime.h>
#include <cstdint>
#include <math.h>

#define BB 4
#define GG 4096
#define HD 1024
#define EE 32
#define CAP 160
#define NTOK (BB*GG)          // 16384

// -------- scratch (static __device__, no allocation) --------
__device__ unsigned int g_mask[NTOK];        // expert mask per token (capacity-pruned after scan)
__device__ int          g_possum[NTOK];      // sum over experts of kept positions
__device__ float        g_weights[NTOK*EE];  // expert_weights (pre-capacity)
__device__ float        g_probs[NTOK*EE];    // raw_gates (softmax probs)
__device__ int          g_density[BB*EE];    // kept count per (b,e) = min(count,CAP)
__device__ float        g_term[BB*EE];       // proxySum * kept

// ============================================================
// Kernel Z: zero-fill via TMA bulk stores. Each block zeroes a
// 64KB smem buffer once, then streams 10 x 64KB cp.async.bulk
// stores (640KB contiguous per block). 1024 blocks cover the
// full 671,088,640-byte dispatch+combine region exactly.
// ============================================================
#define FILL_TPB 256
#define FILL_BLOCKS 1024
#define FILL_SMEM 65536
#define FILL_ITERS 10          // 10 * 64KB = 640KB per block

__global__ __launch_bounds__(FILL_TPB) void fill_kernel(float* __restrict__ out) {
    extern __shared__ float4 zbuf[];
    float4 z = make_float4(0.f, 0.f, 0.f, 0.f);
#pragma unroll
    for (int i = threadIdx.x; i < FILL_SMEM / 16; i += FILL_TPB) zbuf[i] = z;
    __syncthreads();
    asm volatile("fence.proxy.async.shared::cta;" ::: "memory");

    if (threadIdx.x == 0) {
        unsigned int saddr;
        asm("{ .reg .u64 t; cvta.to.shared.u64 t, %1; cvt.u32.u64 %0, t; }"
            : "=r"(saddr) : "l"(zbuf));
        char* g = (char*)out + (size_t)blockIdx.x * ((size_t)FILL_SMEM * FILL_ITERS);
#pragma unroll
        for (int i = 0; i < FILL_ITERS; i++) {
            asm volatile("cp.async.bulk.global.shared::cta.bulk_group [%0], [%1], %2;"
                         :: "l"(g + (size_t)i * FILL_SMEM), "r"(saddr), "n"(FILL_SMEM)
                         : "memory");
            asm volatile("cp.async.bulk.commit_group;" ::: "memory");
        }
        asm volatile("cp.async.bulk.wait_group 0;" ::: "memory");
    }
}

// ============================================================
// Kernel 1: gating — logits GEMM + softmax + stable bitonic
// sort + dynamic-k + weights/mask. 1 warp handles 4 tokens,
// w chunk in registers, x staged in 128KB smem.
// ============================================================
#define TPB 256
#define WARPS 8
#define TPW 4
#define TOKS_BLK (WARPS*TPW)      // 32 tokens/block

extern __shared__ float xs[];     // [32][1024] = 131072 B

__global__ __launch_bounds__(TPB) void gating_kernel(const float* __restrict__ x,
                                                     const float* __restrict__ w) {
    int tid = threadIdx.x;
    int token0 = blockIdx.x * TOKS_BLK;

    const float4* xg = (const float4*)(x + (size_t)token0 * HD);
    float4* xs4 = (float4*)xs;
#pragma unroll
    for (int i = 0; i < 32; i++) xs4[tid + i*TPB] = xg[tid + i*TPB];
    __syncthreads();

    int warp = tid >> 5, lane = tid & 31;
    float a0[TPW], a1[TPW], a2[TPW], a3[TPW];
#pragma unroll
    for (int t = 0; t < TPW; t++) { a0[t]=0.f; a1[t]=0.f; a2[t]=0.f; a3[t]=0.f; }

    const float* wp = w + lane;               // column 'lane' of w [HD][EE]
    for (int c = 0; c < HD; c += 32) {
        float wreg[32];
#pragma unroll
        for (int j = 0; j < 32; j++) wreg[j] = wp[(c + j) * EE];
#pragma unroll
        for (int t = 0; t < TPW; t++) {
            const float* xr = xs + (warp*TPW + t)*HD + c;
#pragma unroll
            for (int j = 0; j < 32; j += 4) {
                float4 xv = *(const float4*)(xr + j);
                a0[t] += xv.x * wreg[j+0];
                a1[t] += xv.y * wreg[j+1];
                a2[t] += xv.z * wreg[j+2];
                a3[t] += xv.w * wreg[j+3];
            }
        }
    }

    float* wsm = xs + warp * (TPW * HD);      // reuse this warp's x region
    int*   ssm = (int*)(wsm + 32);

    for (int t = 0; t < TPW; t++) {
        int token = token0 + warp*TPW + t;
        float logit = (a0[t] + a1[t]) + (a2[t] + a3[t]);

        // softmax across warp (lane = expert)
        float m = logit;
#pragma unroll
        for (int off = 16; off; off >>= 1) m = fmaxf(m, __shfl_xor_sync(~0u, m, off));
        float p = expf(logit - m);
        float s = p;
#pragma unroll
        for (int off = 16; off; off >>= 1) s += __shfl_xor_sync(~0u, s, off);
        p = p / s;
        g_probs[(size_t)token * EE + lane] = p;

        // stable descending bitonic sort: key (p desc, lane asc)
        float v = p; int idx = lane;
#pragma unroll
        for (int k = 2; k <= 32; k <<= 1) {
#pragma unroll
            for (int j = k >> 1; j > 0; j >>= 1) {
                float ov = __shfl_xor_sync(~0u, v,   j);
                int   oi = __shfl_xor_sync(~0u, idx, j);
                bool down   = ((lane & k) == 0);
                bool lower  = ((lane & j) == 0);
                bool ofirst = (ov > v) || (ov == v && oi < idx);
                bool keep_other = down ? (lower == ofirst) : (lower != ofirst);
                if (keep_other) { v = ov; idx = oi; }
            }
        }

        // inclusive cumsum of sorted probs
        float cum = v;
#pragma unroll
        for (int off = 1; off < 32; off <<= 1) {
            float nb = __shfl_up_sync(~0u, cum, off);
            if (lane >= off) cum += nb;
        }
        unsigned bal = __ballot_sync(~0u, cum >= 0.8f);
        int kk = bal ? __ffs(bal) : 32;
        float sel = __shfl_sync(~0u, cum, kk - 1);
        bool selected = (lane < kk);
        float wv = selected ? (v / sel) : 0.0f;

        // scatter sorted->original expert order via smem
        __syncwarp();
        wsm[idx] = wv;
        ssm[idx] = selected ? 1 : 0;
        __syncwarp();
        float myw = wsm[lane];
        int mysel = ssm[lane];
        unsigned word = __ballot_sync(~0u, mysel != 0);
        g_weights[(size_t)token * EE + lane] = myw;
        if (lane == 0) g_mask[token] = word;
        if (lane == 1) g_possum[token] = 0;   // init for scan's atomicAdd
        __syncwarp();
    }
}

// ============================================================
// Kernel 2: per-(b,e) exclusive scan over 4096 tokens,
// capacity truncation, pos_sum accumulation, density count
// ============================================================
__global__ __launch_bounds__(256) void scan_kernel() {
    int e = blockIdx.x & 31;
    int b = blockIdx.x >> 5;
    int tid = threadIdx.x;                // 256 threads, 16 tokens each
    int base = b * GG + tid * 16;

    unsigned bits = 0;
#pragma unroll
    for (int i = 0; i < 16; i++)
        bits |= ((g_mask[base + i] >> e) & 1u) << i;
    int cnt = __popc(bits);

    int lane = tid & 31, wrp = tid >> 5;
    int inc = cnt;
#pragma unroll
    for (int off = 1; off < 32; off <<= 1) {
        int nb = __shfl_up_sync(~0u, inc, off);
        if (lane >= off) inc += nb;
    }
    __shared__ int wsum[8];
    if (lane == 31) wsum[wrp] = inc;
    __syncthreads();
    int wofs = 0, total = 0;
#pragma unroll
    for (int i = 0; i < 8; i++) {
        int v = wsum[i];
        if (i < wrp) wofs += v;
        total += v;
    }
    int run = wofs + inc - cnt;           // exclusive prefix for this thread

    for (int i = 0; i < 16; i++) {
        if ((bits >> i) & 1u) {
            int tok = base + i;
            if (run < CAP) {
                if (run > 0) atomicAdd(&g_possum[tok], run);
            } else {
                atomicAnd(&g_mask[tok], ~(1u << e));   // drop over-capacity
            }
            run++;
        }
    }
    if (tid == 0) g_density[b * EE + e] = (total < CAP) ? total : CAP;
}

// ============================================================
// Kernel 3: scatter nonzeros — one thread per (token, expert)
// ============================================================
__global__ __launch_bounds__(256) void scatter_kernel(float* __restrict__ out, size_t D) {
    int idx = blockIdx.x * blockDim.x + threadIdx.x;   // token*32 + expert
    int tok = idx >> 5;
    int e   = idx & 31;
    if (tok >= NTOK) return;
    unsigned wm = g_mask[tok];
    if (!((wm >> e) & 1u)) return;
    int ps = g_possum[tok];
    if (ps >= CAP) return;
    size_t o = ((size_t)tok * EE + e) * CAP + ps;
    out[o]     = 1.0f;
    out[D + o] = g_weights[(size_t)tok * EE + e];
}

// ============================================================
// Kernel 4: per-(b,e) proxy sum * density  -> term
// ============================================================
__global__ __launch_bounds__(256) void proxy_kernel() {
    int e = blockIdx.x & 31;
    int b = blockIdx.x >> 5;
    int tid = threadIdx.x;
    float s = 0.0f;
    for (int g = tid; g < GG; g += 256)
        s += g_probs[((size_t)(b * GG + g)) * EE + e];
    int lane = tid & 31, wrp = tid >> 5;
#pragma unroll
    for (int off = 16; off; off >>= 1) s += __shfl_xor_sync(~0u, s, off);
    __shared__ float red[8];
    if (lane == 0) red[wrp] = s;
    __syncthreads();
    if (tid == 0) {
        float tot = 0.0f;
#pragma unroll
        for (int i = 0; i < 8; i++) tot += red[i];
        g_term[b * EE + e] = tot * (float)g_density[b * EE + e];
    }
}

// ============================================================
// Kernel 5: final loss = sum(term) * 2^-21  (writes out[2D] only,
// which the fill never touches -> runs before the join)
// ============================================================
__global__ __launch_bounds__(128) void loss_kernel(float* __restrict__ out, size_t D) {
    int tid = threadIdx.x;
    float v = (tid < BB * EE) ? g_term[tid] : 0.0f;
    int lane = tid & 31, wrp = tid >> 5;
#pragma unroll
    for (int off = 16; off; off >>= 1) v += __shfl_xor_sync(~0u, v, off);
    __shared__ float red[4];
    if (lane == 0) red[wrp] = v;
    __syncthreads();
    if (tid == 0) {
        float tot = red[0] + red[1] + red[2] + red[3];
        out[2 * D] = tot * 4.76837158203125e-07f;
    }
}

// ============================================================
extern "C" void kernel_launch(void* const* d_in, const int* in_sizes, int n_in,
                              void* d_out, int out_size) {
    (void)in_sizes; (void)n_in;
    const float* x = (const float*)d_in[0];
    const float* w = (const float*)d_in[1];
    float* out = (float*)d_out;
    size_t D = (size_t)((out_size - 1) / 2);   // dispatch / combine each D elems, loss last

    // Fork: TMA fill on side stream, compute chain on main stream, join for scatter.
    cudaStream_t sZ;
    cudaEvent_t eFork, eJoin;
    cudaStreamCreateWithFlags(&sZ, cudaStreamNonBlocking);
    cudaEventCreateWithFlags(&eFork, cudaEventDisableTiming);
    cudaEventCreateWithFlags(&eJoin, cudaEventDisableTiming);

    cudaEventRecord(eFork, 0);
    cudaStreamWaitEvent(sZ, eFork, 0);
    cudaFuncSetAttribute(fill_kernel,
                         cudaFuncAttributeMaxDynamicSharedMemorySize, FILL_SMEM);
    fill_kernel<<<FILL_BLOCKS, FILL_TPB, FILL_SMEM, sZ>>>(out);
    cudaEventRecord(eJoin, sZ);

    cudaFuncSetAttribute(gating_kernel,
                         cudaFuncAttributeMaxDynamicSharedMemorySize, TOKS_BLK * HD * 4);
    gating_kernel<<<NTOK / TOKS_BLK, TPB, TOKS_BLK * HD * 4>>>(x, w);
    scan_kernel<<<BB * EE, 256>>>();
    proxy_kernel<<<BB * EE, 256>>>();
    loss_kernel<<<1, 128>>>(out, D);          // out[2D] only — independent of fill

    cudaStreamWaitEvent(0, eJoin, 0);
    scatter_kernel<<<(NTOK * EE + 255) / 256, 256>>>(out, D);

    cudaEventDestroy(eFork);
    cudaEventDestroy(eJoin);
    cudaStreamDestroy(sZ);
}

// round 7
// speedup vs baseline: 1.1184x; 1.1184x over previous
#include <cuda_runtime.h>
#include <cstdint>
#include <math.h>

#define BB 4
#define GG 4096
#define HD 1024
#define EE 32
#define CAP 160
#define NTOK (BB*GG)          // 16384
#define MAXENT (BB*EE*CAP)    // 20480 upper bound on kept (tok,e) pairs

// -------- scratch (static __device__, no allocation) --------
__device__ unsigned int g_mask[NTOK];        // expert mask per token (capacity-pruned after scan)
__device__ int          g_possum[NTOK];      // sum over experts of kept positions
__device__ float        g_weights[NTOK*EE];  // expert_weights (pre-capacity)
__device__ float        g_probs[NTOK*EE];    // raw_gates (softmax probs)
__device__ int          g_density[BB*EE];    // kept count per (b,e) = min(count,CAP)
__device__ float        g_term[BB*EE];       // proxySum * kept
__device__ int          g_count;             // compact list size
__device__ unsigned int g_off[MAXENT];       // compact: output offset (< D, fits u32)
__device__ float        g_val[MAXENT];       // compact: combine weight

// ============================================================
// Kernel Z: zero-fill, chunked __stcs float4 (best measured:
// ~2.24 TB/s — at this part's write ceiling). 20480 blocks x
// 32KB contiguous chunk, no bounds checks (exactly divisible).
// ============================================================
#define FILL_TPB 256
#define FILL_CHUNK 8          // float4 per thread -> 32KB per block

__global__ __launch_bounds__(FILL_TPB) void fill_kernel(float4* __restrict__ out) {
    size_t base = (size_t)blockIdx.x * (FILL_TPB * FILL_CHUNK) + threadIdx.x;
    float4 z = make_float4(0.f, 0.f, 0.f, 0.f);
#pragma unroll
    for (int i = 0; i < FILL_CHUNK; i++)
        __stcs(&out[base + (size_t)i * FILL_TPB], z);
}

// ============================================================
// Kernel 1: gating — logits GEMM + softmax + stable bitonic
// sort + dynamic-k + weights/mask. 1 warp handles 4 tokens,
// w chunk in registers, x staged in 128KB smem.
// ============================================================
#define TPB 256
#define WARPS 8
#define TPW 4
#define TOKS_BLK (WARPS*TPW)      // 32 tokens/block

extern __shared__ float xs[];     // [32][1024] = 131072 B

__global__ __launch_bounds__(TPB) void gating_kernel(const float* __restrict__ x,
                                                     const float* __restrict__ w) {
    int tid = threadIdx.x;
    int token0 = blockIdx.x * TOKS_BLK;
    if (blockIdx.x == 0 && tid == 0) g_count = 0;   // reset compact counter each call

    const float4* xg = (const float4*)(x + (size_t)token0 * HD);
    float4* xs4 = (float4*)xs;
#pragma unroll
    for (int i = 0; i < 32; i++) xs4[tid + i*TPB] = xg[tid + i*TPB];
    __syncthreads();

    int warp = tid >> 5, lane = tid & 31;
    float a0[TPW], a1[TPW], a2[TPW], a3[TPW];
#pragma unroll
    for (int t = 0; t < TPW; t++) { a0[t]=0.f; a1[t]=0.f; a2[t]=0.f; a3[t]=0.f; }

    const float* wp = w + lane;               // column 'lane' of w [HD][EE]
    for (int c = 0; c < HD; c += 32) {
        float wreg[32];
#pragma unroll
        for (int j = 0; j < 32; j++) wreg[j] = wp[(c + j) * EE];
#pragma unroll
        for (int t = 0; t < TPW; t++) {
            const float* xr = xs + (warp*TPW + t)*HD + c;
#pragma unroll
            for (int j = 0; j < 32; j += 4) {
                float4 xv = *(const float4*)(xr + j);
                a0[t] += xv.x * wreg[j+0];
                a1[t] += xv.y * wreg[j+1];
                a2[t] += xv.z * wreg[j+2];
                a3[t] += xv.w * wreg[j+3];
            }
        }
    }

    float* wsm = xs + warp * (TPW * HD);      // reuse this warp's x region
    int*   ssm = (int*)(wsm + 32);

    for (int t = 0; t < TPW; t++) {
        int token = token0 + warp*TPW + t;
        float logit = (a0[t] + a1[t]) + (a2[t] + a3[t]);

        // softmax across warp (lane = expert)
        float m = logit;
#pragma unroll
        for (int off = 16; off; off >>= 1) m = fmaxf(m, __shfl_xor_sync(~0u, m, off));
        float p = expf(logit - m);
        float s = p;
#pragma unroll
        for (int off = 16; off; off >>= 1) s += __shfl_xor_sync(~0u, s, off);
        p = p / s;
        g_probs[(size_t)token * EE + lane] = p;

        // stable descending bitonic sort: key (p desc, lane asc)
        float v = p; int idx = lane;
#pragma unroll
        for (int k = 2; k <= 32; k <<= 1) {
#pragma unroll
            for (int j = k >> 1; j > 0; j >>= 1) {
                float ov = __shfl_xor_sync(~0u, v,   j);
                int   oi = __shfl_xor_sync(~0u, idx, j);
                bool down   = ((lane & k) == 0);
                bool lower  = ((lane & j) == 0);
                bool ofirst = (ov > v) || (ov == v && oi < idx);
                bool keep_other = down ? (lower == ofirst) : (lower != ofirst);
                if (keep_other) { v = ov; idx = oi; }
            }
        }

        // inclusive cumsum of sorted probs
        float cum = v;
#pragma unroll
        for (int off = 1; off < 32; off <<= 1) {
            float nb = __shfl_up_sync(~0u, cum, off);
            if (lane >= off) cum += nb;
        }
        unsigned bal = __ballot_sync(~0u, cum >= 0.8f);
        int kk = bal ? __ffs(bal) : 32;
        float sel = __shfl_sync(~0u, cum, kk - 1);
        bool selected = (lane < kk);
        float wv = selected ? (v / sel) : 0.0f;

        // scatter sorted->original expert order via smem
        __syncwarp();
        wsm[idx] = wv;
        ssm[idx] = selected ? 1 : 0;
        __syncwarp();
        float myw = wsm[lane];
        int mysel = ssm[lane];
        unsigned word = __ballot_sync(~0u, mysel != 0);
        g_weights[(size_t)token * EE + lane] = myw;
        if (lane == 0) g_mask[token] = word;
        if (lane == 1) g_possum[token] = 0;   // init for scan's atomicAdd
        __syncwarp();
    }
}

// ============================================================
// Kernel 2: per-(b,e) exclusive scan over 4096 tokens,
// capacity truncation, pos_sum accumulation, density count
// ============================================================
__global__ __launch_bounds__(256) void scan_kernel() {
    int e = blockIdx.x & 31;
    int b = blockIdx.x >> 5;
    int tid = threadIdx.x;                // 256 threads, 16 tokens each
    int base = b * GG + tid * 16;

    unsigned bits = 0;
#pragma unroll
    for (int i = 0; i < 16; i++)
        bits |= ((g_mask[base + i] >> e) & 1u) << i;
    int cnt = __popc(bits);

    int lane = tid & 31, wrp = tid >> 5;
    int inc = cnt;
#pragma unroll
    for (int off = 1; off < 32; off <<= 1) {
        int nb = __shfl_up_sync(~0u, inc, off);
        if (lane >= off) inc += nb;
    }
    __shared__ int wsum[8];
    if (lane == 31) wsum[wrp] = inc;
    __syncthreads();
    int wofs = 0, total = 0;
#pragma unroll
    for (int i = 0; i < 8; i++) {
        int v = wsum[i];
        if (i < wrp) wofs += v;
        total += v;
    }
    int run = wofs + inc - cnt;           // exclusive prefix for this thread

    for (int i = 0; i < 16; i++) {
        if ((bits >> i) & 1u) {
            int tok = base + i;
            if (run < CAP) {
                if (run > 0) atomicAdd(&g_possum[tok], run);
            } else {
                atomicAnd(&g_mask[tok], ~(1u << e));   // drop over-capacity
            }
            run++;
        }
    }
    if (tid == 0) g_density[b * EE + e] = (total < CAP) ? total : CAP;
}

// ============================================================
// Kernel 2b: compact — build dense (offset, weight) write list.
// Runs on main stream, hidden under the fill. One thread/token.
// ============================================================
__global__ __launch_bounds__(256) void compact_kernel() {
    int tok = blockIdx.x * blockDim.x + threadIdx.x;
    if (tok >= NTOK) return;
    unsigned wm = g_mask[tok];
    if (!wm) return;
    int ps = g_possum[tok];
    if (ps >= CAP) return;
    int n = __popc(wm);
    int slot = atomicAdd(&g_count, n);
    while (wm) {
        int e = __ffs(wm) - 1;
        wm &= wm - 1;
        g_off[slot] = (unsigned int)(((size_t)tok * EE + e) * CAP + ps);
        g_val[slot] = g_weights[(size_t)tok * EE + e];
        slot++;
    }
}

// ============================================================
// Kernel 3 (post-join): streamed scatter from compact list
// ============================================================
__global__ __launch_bounds__(256) void scatter_list_kernel(float* __restrict__ out, size_t D) {
    int i = blockIdx.x * blockDim.x + threadIdx.x;
    if (i >= g_count) return;
    size_t o = g_off[i];
    out[o]     = 1.0f;
    out[D + o] = g_val[i];
}

// ============================================================
// Kernel 4: per-(b,e) proxy sum * density  -> term
// ============================================================
__global__ __launch_bounds__(256) void proxy_kernel() {
    int e = blockIdx.x & 31;
    int b = blockIdx.x >> 5;
    int tid = threadIdx.x;
    float s = 0.0f;
    for (int g = tid; g < GG; g += 256)
        s += g_probs[((size_t)(b * GG + g)) * EE + e];
    int lane = tid & 31, wrp = tid >> 5;
#pragma unroll
    for (int off = 16; off; off >>= 1) s += __shfl_xor_sync(~0u, s, off);
    __shared__ float red[8];
    if (lane == 0) red[wrp] = s;
    __syncthreads();
    if (tid == 0) {
        float tot = 0.0f;
#pragma unroll
        for (int i = 0; i < 8; i++) tot += red[i];
        g_term[b * EE + e] = tot * (float)g_density[b * EE + e];
    }
}

// ============================================================
// Kernel 5: final loss = sum(term) * 2^-21  (writes out[2D] only,
// which the fill never touches -> runs before the join)
// ============================================================
__global__ __launch_bounds__(128) void loss_kernel(float* __restrict__ out, size_t D) {
    int tid = threadIdx.x;
    float v = (tid < BB * EE) ? g_term[tid] : 0.0f;
    int lane = tid & 31, wrp = tid >> 5;
#pragma unroll
    for (int off = 16; off; off >>= 1) v += __shfl_xor_sync(~0u, v, off);
    __shared__ float red[4];
    if (lane == 0) red[wrp] = v;
    __syncthreads();
    if (tid == 0) {
        float tot = red[0] + red[1] + red[2] + red[3];
        out[2 * D] = tot * 4.76837158203125e-07f;
    }
}

// ============================================================
extern "C" void kernel_launch(void* const* d_in, const int* in_sizes, int n_in,
                              void* d_out, int out_size) {
    (void)in_sizes; (void)n_in;
    const float* x = (const float*)d_in[0];
    const float* w = (const float*)d_in[1];
    float* out = (float*)d_out;
    size_t D = (size_t)((out_size - 1) / 2);   // dispatch / combine each D elems, loss last

    // 2*D floats = 167,772,160 = 20480 blocks * 2048 float4 exactly
    int fill_blocks = (int)((2 * D) / (FILL_TPB * FILL_CHUNK * 4));

    // Fork: fill on side stream; compute chain (incl. compact + loss) hidden
    // under it on the main stream; join only for the streamed scatter.
    cudaStream_t sZ;
    cudaEvent_t eFork, eJoin;
    cudaStreamCreateWithFlags(&sZ, cudaStreamNonBlocking);
    cudaEventCreateWithFlags(&eFork, cudaEventDisableTiming);
    cudaEventCreateWithFlags(&eJoin, cudaEventDisableTiming);

    cudaEventRecord(eFork, 0);
    cudaStreamWaitEvent(sZ, eFork, 0);
    fill_kernel<<<fill_blocks, FILL_TPB, 0, sZ>>>((float4*)out);
    cudaEventRecord(eJoin, sZ);

    cudaFuncSetAttribute(gating_kernel,
                         cudaFuncAttributeMaxDynamicSharedMemorySize, TOKS_BLK * HD * 4);
    gating_kernel<<<NTOK / TOKS_BLK, TPB, TOKS_BLK * HD * 4>>>(x, w);
    scan_kernel<<<BB * EE, 256>>>();
    compact_kernel<<<NTOK / 256, 256>>>();
    proxy_kernel<<<BB * EE, 256>>>();
    loss_kernel<<<1, 128>>>(out, D);          // out[2D] only — independent of fill

    cudaStreamWaitEvent(0, eJoin, 0);
    scatter_list_kernel<<<MAXENT / 256, 256>>>(out, D);

    cudaEventDestroy(eFork);
    cudaEventDestroy(eJoin);
    cudaStreamDestroy(sZ);
}

// round 8
// speedup vs baseline: 1.1545x; 1.0323x over previous
#include <cuda_runtime.h>
#include <cstdint>
#include <math.h>

#define BB 4
#define GG 4096
#define HD 1024
#define EE 32
#define CAP 160
#define NTOK (BB*GG)          // 16384

// -------- scratch (static __device__, no allocation) --------
__device__ unsigned int g_mask[NTOK];        // expert mask per token (capacity-pruned after scan)
__device__ int          g_possum[NTOK];      // sum over experts of kept positions
__device__ float        g_weights[NTOK*EE];  // expert_weights (pre-capacity)
__device__ float        g_probs[NTOK*EE];    // raw_gates (softmax probs)
__device__ int          g_density[BB*EE];    // kept count per (b,e) = min(count,CAP)
__device__ float        g_term[BB*EE];       // proxySum * kept

// ============================================================
// Kernel Z: zero-fill, chunked __stcs float4 (best measured:
// ~2.24 TB/s, at this part's write ceiling). 20480 blocks x
// 32KB contiguous chunk, no bounds checks (exactly divisible).
// ============================================================
#define FILL_TPB 256
#define FILL_CHUNK 8          // float4 per thread -> 32KB per block

__global__ __launch_bounds__(FILL_TPB) void fill_kernel(float4* __restrict__ out) {
    size_t base = (size_t)blockIdx.x * (FILL_TPB * FILL_CHUNK) + threadIdx.x;
    float4 z = make_float4(0.f, 0.f, 0.f, 0.f);
#pragma unroll
    for (int i = 0; i < FILL_CHUNK; i++)
        __stcs(&out[base + (size_t)i * FILL_TPB], z);
}

// ============================================================
// Kernel 1: gating — logits GEMM + softmax + stable bitonic
// sort + dynamic-k + weights/mask. Streaming loads (__ldcs) so
// the 67MB x-read doesn't evict the fill's L2 write lines.
// ============================================================
#define TPB 256
#define WARPS 8
#define TPW 4
#define TOKS_BLK (WARPS*TPW)      // 32 tokens/block

extern __shared__ float xs[];     // [32][1024] = 131072 B

__global__ __launch_bounds__(TPB) void gating_kernel(const float* __restrict__ x,
                                                     const float* __restrict__ w) {
    int tid = threadIdx.x;
    int token0 = blockIdx.x * TOKS_BLK;

    const float4* xg = (const float4*)(x + (size_t)token0 * HD);
    float4* xs4 = (float4*)xs;
#pragma unroll
    for (int i = 0; i < 32; i++) xs4[tid + i*TPB] = __ldcs(&xg[tid + i*TPB]);
    __syncthreads();

    int warp = tid >> 5, lane = tid & 31;
    float a0[TPW], a1[TPW], a2[TPW], a3[TPW];
#pragma unroll
    for (int t = 0; t < TPW; t++) { a0[t]=0.f; a1[t]=0.f; a2[t]=0.f; a3[t]=0.f; }

    const float* wp = w + lane;               // column 'lane' of w [HD][EE]
    for (int c = 0; c < HD; c += 32) {
        float wreg[32];
#pragma unroll
        for (int j = 0; j < 32; j++) wreg[j] = wp[(c + j) * EE];
#pragma unroll
        for (int t = 0; t < TPW; t++) {
            const float* xr = xs + (warp*TPW + t)*HD + c;
#pragma unroll
            for (int j = 0; j < 32; j += 4) {
                float4 xv = *(const float4*)(xr + j);
                a0[t] += xv.x * wreg[j+0];
                a1[t] += xv.y * wreg[j+1];
                a2[t] += xv.z * wreg[j+2];
                a3[t] += xv.w * wreg[j+3];
            }
        }
    }

    float* wsm = xs + warp * (TPW * HD);      // reuse this warp's x region
    int*   ssm = (int*)(wsm + 32);

    for (int t = 0; t < TPW; t++) {
        int token = token0 + warp*TPW + t;
        float logit = (a0[t] + a1[t]) + (a2[t] + a3[t]);

        // softmax across warp (lane = expert)
        float m = logit;
#pragma unroll
        for (int off = 16; off; off >>= 1) m = fmaxf(m, __shfl_xor_sync(~0u, m, off));
        float p = expf(logit - m);
        float s = p;
#pragma unroll
        for (int off = 16; off; off >>= 1) s += __shfl_xor_sync(~0u, s, off);
        p = p / s;
        __stcs(&g_probs[(size_t)token * EE + lane], p);

        // stable descending bitonic sort: key (p desc, lane asc)
        float v = p; int idx = lane;
#pragma unroll
        for (int k = 2; k <= 32; k <<= 1) {
#pragma unroll
            for (int j = k >> 1; j > 0; j >>= 1) {
                float ov = __shfl_xor_sync(~0u, v,   j);
                int   oi = __shfl_xor_sync(~0u, idx, j);
                bool down   = ((lane & k) == 0);
                bool lower  = ((lane & j) == 0);
                bool ofirst = (ov > v) || (ov == v && oi < idx);
                bool keep_other = down ? (lower == ofirst) : (lower != ofirst);
                if (keep_other) { v = ov; idx = oi; }
            }
        }

        // inclusive cumsum of sorted probs
        float cum = v;
#pragma unroll
        for (int off = 1; off < 32; off <<= 1) {
            float nb = __shfl_up_sync(~0u, cum, off);
            if (lane >= off) cum += nb;
        }
        unsigned bal = __ballot_sync(~0u, cum >= 0.8f);
        int kk = bal ? __ffs(bal) : 32;
        float sel = __shfl_sync(~0u, cum, kk - 1);
        bool selected = (lane < kk);
        float wv = selected ? (v / sel) : 0.0f;

        // scatter sorted->original expert order via smem
        __syncwarp();
        wsm[idx] = wv;
        ssm[idx] = selected ? 1 : 0;
        __syncwarp();
        float myw = wsm[lane];
        int mysel = ssm[lane];
        unsigned word = __ballot_sync(~0u, mysel != 0);
        __stcs(&g_weights[(size_t)token * EE + lane], myw);
        if (lane == 0) g_mask[token] = word;
        if (lane == 1) g_possum[token] = 0;   // init for scan's atomicAdd
        __syncwarp();
    }
}

// ============================================================
// Kernel 2: per-(b,e) exclusive scan over 4096 tokens,
// capacity truncation, pos_sum accumulation, density count
// ============================================================
__global__ __launch_bounds__(256) void scan_kernel() {
    int e = blockIdx.x & 31;
    int b = blockIdx.x >> 5;
    int tid = threadIdx.x;                // 256 threads, 16 tokens each
    int base = b * GG + tid * 16;

    unsigned bits = 0;
#pragma unroll
    for (int i = 0; i < 16; i++)
        bits |= ((g_mask[base + i] >> e) & 1u) << i;
    int cnt = __popc(bits);

    int lane = tid & 31, wrp = tid >> 5;
    int inc = cnt;
#pragma unroll
    for (int off = 1; off < 32; off <<= 1) {
        int nb = __shfl_up_sync(~0u, inc, off);
        if (lane >= off) inc += nb;
    }
    __shared__ int wsum[8];
    if (lane == 31) wsum[wrp] = inc;
    __syncthreads();
    int wofs = 0, total = 0;
#pragma unroll
    for (int i = 0; i < 8; i++) {
        int v = wsum[i];
        if (i < wrp) wofs += v;
        total += v;
    }
    int run = wofs + inc - cnt;           // exclusive prefix for this thread

    for (int i = 0; i < 16; i++) {
        if ((bits >> i) & 1u) {
            int tok = base + i;
            if (run < CAP) {
                if (run > 0) atomicAdd(&g_possum[tok], run);
            } else {
                atomicAnd(&g_mask[tok], ~(1u << e));   // drop over-capacity
            }
            run++;
        }
    }
    if (tid == 0) g_density[b * EE + e] = (total < CAP) ? total : CAP;
}

// ============================================================
// Kernel 3 (post-join): scatter — one thread per (token, expert)
// ============================================================
__global__ __launch_bounds__(256) void scatter_kernel(float* __restrict__ out, size_t D) {
    int idx = blockIdx.x * blockDim.x + threadIdx.x;   // token*32 + expert
    int tok = idx >> 5;
    int e   = idx & 31;
    if (tok >= NTOK) return;
    unsigned wm = g_mask[tok];
    if (!((wm >> e) & 1u)) return;
    int ps = g_possum[tok];
    if (ps >= CAP) return;
    size_t o = ((size_t)tok * EE + e) * CAP + ps;
    out[o]     = 1.0f;
    out[D + o] = g_weights[(size_t)tok * EE + e];
}

// ============================================================
// Kernel 4: per-(b,e) proxy sum * density  -> term
// ============================================================
__global__ __launch_bounds__(256) void proxy_kernel() {
    int e = blockIdx.x & 31;
    int b = blockIdx.x >> 5;
    int tid = threadIdx.x;
    float s = 0.0f;
    for (int g = tid; g < GG; g += 256)
        s += __ldcs(&g_probs[((size_t)(b * GG + g)) * EE + e]);
    int lane = tid & 31, wrp = tid >> 5;
#pragma unroll
    for (int off = 16; off; off >>= 1) s += __shfl_xor_sync(~0u, s, off);
    __shared__ float red[8];
    if (lane == 0) red[wrp] = s;
    __syncthreads();
    if (tid == 0) {
        float tot = 0.0f;
#pragma unroll
        for (int i = 0; i < 8; i++) tot += red[i];
        g_term[b * EE + e] = tot * (float)g_density[b * EE + e];
    }
}

// ============================================================
// Kernel 5: final loss = sum(term) * 2^-21  (writes out[2D] only,
// which the fill never touches -> runs before the join)
// ============================================================
__global__ __launch_bounds__(128) void loss_kernel(float* __restrict__ out, size_t D) {
    int tid = threadIdx.x;
    float v = (tid < BB * EE) ? g_term[tid] : 0.0f;
    int lane = tid & 31, wrp = tid >> 5;
#pragma unroll
    for (int off = 16; off; off >>= 1) v += __shfl_xor_sync(~0u, v, off);
    __shared__ float red[4];
    if (lane == 0) red[wrp] = v;
    __syncthreads();
    if (tid == 0) {
        float tot = red[0] + red[1] + red[2] + red[3];
        out[2 * D] = tot * 4.76837158203125e-07f;
    }
}

// ============================================================
extern "C" void kernel_launch(void* const* d_in, const int* in_sizes, int n_in,
                              void* d_out, int out_size) {
    (void)in_sizes; (void)n_in;
    const float* x = (const float*)d_in[0];
    const float* w = (const float*)d_in[1];
    float* out = (float*)d_out;
    size_t D = (size_t)((out_size - 1) / 2);   // dispatch / combine each D elems, loss last

    // 2*D floats = 167,772,160 = 20480 blocks * 2048 float4 exactly
    int fill_blocks = (int)((2 * D) / (FILL_TPB * FILL_CHUNK * 4));

    // Fork: fill on a HIGH-PRIORITY side stream (fill is the critical path;
    // compute has ~250us of slack). Join only for the scatter.
    int prLo = 0, prHi = 0;
    cudaDeviceGetStreamPriorityRange(&prLo, &prHi);
    cudaStream_t sZ;
    cudaEvent_t eFork, eJoin;
    cudaStreamCreateWithPriority(&sZ, cudaStreamNonBlocking, prHi);
    cudaEventCreateWithFlags(&eFork, cudaEventDisableTiming);
    cudaEventCreateWithFlags(&eJoin, cudaEventDisableTiming);

    cudaEventRecord(eFork, 0);
    cudaStreamWaitEvent(sZ, eFork, 0);
    fill_kernel<<<fill_blocks, FILL_TPB, 0, sZ>>>((float4*)out);
    cudaEventRecord(eJoin, sZ);

    cudaFuncSetAttribute(gating_kernel,
                         cudaFuncAttributeMaxDynamicSharedMemorySize, TOKS_BLK * HD * 4);
    gating_kernel<<<NTOK / TOKS_BLK, TPB, TOKS_BLK * HD * 4>>>(x, w);
    scan_kernel<<<BB * EE, 256>>>();
    proxy_kernel<<<BB * EE, 256>>>();
    loss_kernel<<<1, 128>>>(out, D);          // out[2D] only — independent of fill

    cudaStreamWaitEvent(0, eJoin, 0);
    scatter_kernel<<<(NTOK * EE + 255) / 256, 256>>>(out, D);

    cudaEventDestroy(eFork);
    cudaEventDestroy(eJoin);
    cudaStreamDestroy(sZ);
}